// round 2
// baseline (speedup 1.0000x reference)
#include <cuda_runtime.h>

// ---- problem constants (fixed by setup_inputs) ----
#define N_B   2
#define L_DIM 4800
#define S_DIM 4800
#define C_DIM 256
#define H0 60
#define W0 80
#define H1 60
#define W1 80
#define BRD 2
#define THR_V 0.2f
// sim = dot(feat0,feat1) / (C * temp) = dot / 25.6 ; 1/25.6 = 0.0390625 (exact)
#define SIM_SCALE 0.0390625f

// ---- scratch (device globals; no allocations allowed) ----
__device__ float g_rowsum[N_B * L_DIM];
__device__ float g_colsum[N_B * S_DIM];
__device__ float g_invrow[N_B * L_DIM];
__device__ float g_invcol[N_B * S_DIM];
__device__ float g_rowmax[N_B * L_DIM];
__device__ int   g_rowidx[N_B * L_DIM];
__device__ float g_colmax[N_B * S_DIM];

// ---------------------------------------------------------------------------
// 0) zero the accumulators (graph replays require explicit reset every call)
// ---------------------------------------------------------------------------
__global__ void zero_kernel() {
    int i = blockIdx.x * 256 + threadIdx.x;
    if (i < N_B * L_DIM) { g_rowsum[i] = 0.0f; g_colsum[i] = 0.0f; }
}

// ---------------------------------------------------------------------------
// 1) GEMM + exp epilogue.
//    E[n,l,s] = exp(dot(A[n,l,:], B[n,s,:]) * SIM_SCALE), written into the
//    conf region of d_out (in-place scratch). Row/col sums of E accumulated
//    via shared-memory partials + global atomicAdd.
// ---------------------------------------------------------------------------
#define BM 128
#define BN 128
#define BK 16

__global__ __launch_bounds__(256, 2)
void gemm_exp_kernel(const float* __restrict__ A,
                     const float* __restrict__ B,
                     float* __restrict__ E) {
    const int n    = blockIdx.z;
    const int brow = blockIdx.y * BM;
    const int bcol = blockIdx.x * BN;

    __shared__ float As[BK][BM];
    __shared__ float Bs[BK][BN];
    __shared__ float sRow[BM];
    __shared__ float sCol[BN];

    const int tid = threadIdx.x;           // 256 threads
    const int tx  = tid & 15;              // 0..15
    const int ty  = tid >> 4;              // 0..15

    const float* Ab = A + (size_t)n * L_DIM * C_DIM;
    const float* Bb = B + (size_t)n * S_DIM * C_DIM;

    // accumulators: rows {ty*4..+3, 64+ty*4..+3}, cols {tx*4..+3, 64+tx*4..+3}
    float acc[2][2][4][4];
    #pragma unroll
    for (int a = 0; a < 2; a++)
        #pragma unroll
        for (int b = 0; b < 2; b++)
            #pragma unroll
            for (int i = 0; i < 4; i++)
                #pragma unroll
                for (int j = 0; j < 4; j++) acc[a][b][i][j] = 0.0f;

    // load mapping: each thread loads 2 float4 from A and 2 from B per k-tile
    const int ldRow = tid >> 2;            // 0..63
    const int ldCol = (tid & 3) * 4;       // 0,4,8,12

    for (int k0 = 0; k0 < C_DIM; k0 += BK) {
        #pragma unroll
        for (int h = 0; h < 2; h++) {
            int r  = ldRow + h * 64;
            int gr = brow + r;
            float4 v = (gr < L_DIM)
                ? *(const float4*)(Ab + (size_t)gr * C_DIM + k0 + ldCol)
                : make_float4(0.f, 0.f, 0.f, 0.f);
            As[ldCol + 0][r] = v.x; As[ldCol + 1][r] = v.y;
            As[ldCol + 2][r] = v.z; As[ldCol + 3][r] = v.w;
        }
        #pragma unroll
        for (int h = 0; h < 2; h++) {
            int r  = ldRow + h * 64;
            int gc = bcol + r;
            float4 v = (gc < S_DIM)
                ? *(const float4*)(Bb + (size_t)gc * C_DIM + k0 + ldCol)
                : make_float4(0.f, 0.f, 0.f, 0.f);
            Bs[ldCol + 0][r] = v.x; Bs[ldCol + 1][r] = v.y;
            Bs[ldCol + 2][r] = v.z; Bs[ldCol + 3][r] = v.w;
        }
        __syncthreads();

        #pragma unroll
        for (int k = 0; k < BK; k++) {
            float4 a0 = *(const float4*)&As[k][ty * 4];
            float4 a1 = *(const float4*)&As[k][64 + ty * 4];
            float4 b0 = *(const float4*)&Bs[k][tx * 4];
            float4 b1 = *(const float4*)&Bs[k][64 + tx * 4];
            const float ar[2][4] = {{a0.x, a0.y, a0.z, a0.w}, {a1.x, a1.y, a1.z, a1.w}};
            const float br[2][4] = {{b0.x, b0.y, b0.z, b0.w}, {b1.x, b1.y, b1.z, b1.w}};
            #pragma unroll
            for (int ri = 0; ri < 2; ri++)
                #pragma unroll
                for (int ci = 0; ci < 2; ci++)
                    #pragma unroll
                    for (int i = 0; i < 4; i++)
                        #pragma unroll
                        for (int j = 0; j < 4; j++)
                            acc[ri][ci][i][j] = fmaf(ar[ri][i], br[ci][j], acc[ri][ci][i][j]);
        }
        __syncthreads();
    }

    // ---- epilogue: exp, store E, partial row/col sums ----
    if (tid < BM) sRow[tid] = 0.0f;
    if (tid < BN) sCol[tid] = 0.0f;
    __syncthreads();

    float* Eb = E + (size_t)n * L_DIM * S_DIM;
    float colpart[2][4];
    #pragma unroll
    for (int ci = 0; ci < 2; ci++)
        #pragma unroll
        for (int j = 0; j < 4; j++) colpart[ci][j] = 0.0f;

    #pragma unroll
    for (int ri = 0; ri < 2; ri++) {
        #pragma unroll
        for (int i = 0; i < 4; i++) {
            const int r  = ri * 64 + ty * 4 + i;
            const int gr = brow + r;
            float rowpart = 0.0f;
            if (gr < L_DIM) {
                #pragma unroll
                for (int ci = 0; ci < 2; ci++) {
                    const int c0 = ci * 64 + tx * 4;
                    const int gc = bcol + c0;
                    if (gc < S_DIM) {           // 4800 % 4 == 0: whole float4 in/out
                        float4 ev;
                        ev.x = expf(acc[ri][ci][i][0] * SIM_SCALE);
                        ev.y = expf(acc[ri][ci][i][1] * SIM_SCALE);
                        ev.z = expf(acc[ri][ci][i][2] * SIM_SCALE);
                        ev.w = expf(acc[ri][ci][i][3] * SIM_SCALE);
                        *(float4*)(Eb + (size_t)gr * S_DIM + gc) = ev;
                        rowpart += ev.x + ev.y + ev.z + ev.w;
                        colpart[ci][0] += ev.x; colpart[ci][1] += ev.y;
                        colpart[ci][2] += ev.z; colpart[ci][3] += ev.w;
                    }
                }
                atomicAdd(&sRow[r], rowpart);
            }
        }
    }
    #pragma unroll
    for (int ci = 0; ci < 2; ci++)
        #pragma unroll
        for (int j = 0; j < 4; j++)
            atomicAdd(&sCol[ci * 64 + tx * 4 + j], colpart[ci][j]);
    __syncthreads();

    if (tid < BM) {
        int gr = brow + tid;
        if (gr < L_DIM) atomicAdd(&g_rowsum[n * L_DIM + gr], sRow[tid]);
    }
    if (tid < BN) {
        int gc = bcol + tid;
        if (gc < S_DIM) atomicAdd(&g_colsum[n * S_DIM + gc], sCol[tid]);
    }
}

// ---------------------------------------------------------------------------
// 2) reciprocals of the sums
// ---------------------------------------------------------------------------
__global__ void inv_kernel() {
    int i = blockIdx.x * 256 + threadIdx.x;
    if (i < N_B * L_DIM) {
        g_invrow[i] = 1.0f / g_rowsum[i];
        g_invcol[i] = 1.0f / g_colsum[i];
    }
}

// ---------------------------------------------------------------------------
// 3) row pass: conf = (E*invr)*(E*invc), in place; per-row max + argmax
//    (tie broken toward smallest column index, matching jnp.argmax)
// ---------------------------------------------------------------------------
__global__ __launch_bounds__(256)
void row_pass_kernel(float* __restrict__ conf) {
    const int row = blockIdx.x;              // 0 .. N_B*L_DIM-1
    const int n   = row / L_DIM;
    const int l   = row % L_DIM;
    const float invr = g_invrow[row];
    float* c = conf + (size_t)n * L_DIM * S_DIM + (size_t)l * S_DIM;
    const float* invc = &g_invcol[n * S_DIM];

    float best = -1.0f;
    int   bidx = 0;
    for (int s = threadIdx.x; s < S_DIM; s += 256) {
        float e = c[s];
        float v = (e * invr) * (e * invc[s]);
        c[s] = v;
        if (v > best) { best = v; bidx = s; }   // strided: keeps smallest s on tie
    }

    __shared__ float sv[256];
    __shared__ int   si[256];
    sv[threadIdx.x] = best;
    si[threadIdx.x] = bidx;
    __syncthreads();
    for (int o = 128; o > 0; o >>= 1) {
        if (threadIdx.x < o) {
            float v2 = sv[threadIdx.x + o];
            int   i2 = si[threadIdx.x + o];
            if (v2 > sv[threadIdx.x] ||
                (v2 == sv[threadIdx.x] && i2 < si[threadIdx.x])) {
                sv[threadIdx.x] = v2;
                si[threadIdx.x] = i2;
            }
        }
        __syncthreads();
    }
    if (threadIdx.x == 0) {
        g_rowmax[row] = sv[0];
        g_rowidx[row] = si[0];
    }
}

// ---------------------------------------------------------------------------
// 4) column pass: colmax over l, coalesced reads (thread = one column)
// ---------------------------------------------------------------------------
__global__ __launch_bounds__(256)
void col_pass_kernel(const float* __restrict__ conf) {
    const int s = blockIdx.x * 256 + threadIdx.x;
    const int n = blockIdx.y;
    if (s >= S_DIM) return;
    const float* c = conf + (size_t)n * L_DIM * S_DIM + s;
    float m = 0.0f;
    #pragma unroll 8
    for (int l = 0; l < L_DIM; l++)
        m = fmaxf(m, __ldg(c + (size_t)l * S_DIM));
    g_colmax[n * S_DIM + s] = m;
}

// ---------------------------------------------------------------------------
// 5) match extraction: the only possible True in a row's mask is at its
//    conf-argmax (mask requires conf == rowmax), so this is O(1) per row.
//    Writes mask_v, j_ids, mkpts1_c, mconf (as float32) into the tail.
// ---------------------------------------------------------------------------
__global__ void match_kernel(float* __restrict__ out) {
    const int i = blockIdx.x * 256 + threadIdx.x;   // 0 .. N_B*L_DIM-1
    if (i >= N_B * L_DIM) return;
    const int n = i / L_DIM;
    const int l = i % L_DIM;

    const float v = g_rowmax[i];
    const int   j = g_rowidx[i];

    const int y0 = l / W0, x0 = l % W0;
    const int y1 = j / W1, x1 = j % W1;
    const bool b0 = (y0 >= BRD) && (y0 < H0 - BRD) && (x0 >= BRD) && (x0 < W0 - BRD);
    const bool b1 = (y1 >= BRD) && (y1 < H1 - BRD) && (x1 >= BRD) && (x1 < W1 - BRD);
    const bool mv = (v > THR_V) && b0 && b1 && (v == g_colmax[n * S_DIM + j]);

    const int jid = mv ? j : 0;                      // jnp.argmax(all-False) == 0

    const size_t base = (size_t)N_B * L_DIM * S_DIM; // end of conf region
    const int NL = N_B * L_DIM;
    out[base + i]                    = mv ? 1.0f : 0.0f;       // mask_v
    out[base + NL + i]               = (float)jid;             // j_ids
    out[base + 2 * NL + 2 * i]       = (float)(jid % W1);      // mkpts1_c x
    out[base + 2 * NL + 2 * i + 1]   = (float)(jid / W1);      // mkpts1_c y
    out[base + 4 * NL + i]           = mv ? v : 0.0f;          // mconf
}

// ---------------------------------------------------------------------------
// launch
// ---------------------------------------------------------------------------
extern "C" void kernel_launch(void* const* d_in, const int* in_sizes, int n_in,
                              void* d_out, int out_size) {
    const float* feat0 = (const float*)d_in[0];
    const float* feat1 = (const float*)d_in[1];
    float* out = (float*)d_out;

    // 0) reset accumulators (required for graph replay determinism)
    zero_kernel<<<(N_B * L_DIM + 255) / 256, 256>>>();

    // 1) GEMM + exp -> E written into conf region of d_out
    dim3 gGrid((S_DIM + BN - 1) / BN, (L_DIM + BM - 1) / BM, N_B);
    gemm_exp_kernel<<<gGrid, 256>>>(feat0, feat1, out);

    // 2) reciprocals
    inv_kernel<<<(N_B * L_DIM + 255) / 256, 256>>>();

    // 3) row pass (in-place E -> conf, rowmax/argmax)
    row_pass_kernel<<<N_B * L_DIM, 256>>>(out);

    // 4) column max
    dim3 cGrid((S_DIM + 255) / 256, N_B);
    col_pass_kernel<<<cGrid, 256>>>(out);

    // 5) match extraction tail outputs
    match_kernel<<<(N_B * L_DIM + 255) / 256, 256>>>(out);
}

// round 4
// speedup vs baseline: 2.5932x; 2.5932x over previous
#include <cuda_runtime.h>
#include <cuda_bf16.h>
#include <cstdint>

// ---- problem constants (fixed by setup_inputs) ----
#define N_B   2
#define L_DIM 4800
#define S_DIM 4800
#define C_DIM 256
#define L_PAD 4864            // 38 * 128
#define H0 60
#define W0 80
#define H1 60
#define W1 80
#define BRD 2
#define THR_V 0.2f
#define SIM_SCALE 0.0390625f  // 1/25.6 exact

#define NTILES 38             // L_PAD / 128

// ---- scratch (device globals; no allocations allowed) ----
__device__ __align__(16) float g_rowsum[N_B * L_DIM];
__device__ __align__(16) float g_colsum[N_B * S_DIM];
__device__ __align__(16) float g_invrow[N_B * L_DIM];
__device__ __align__(16) float g_invcol[N_B * S_DIM];
__device__ __align__(16) float g_colmax[N_B * S_DIM];
__device__ __align__(16) unsigned long long g_rowpack[N_B * L_DIM];

// split-precision bf16 operands, rows padded to L_PAD with zeros (statics are
// zero-initialized; pad region never written, stays zero)
__device__ __align__(16) __nv_bfloat16 g_Ahi[N_B * L_PAD * C_DIM];
__device__ __align__(16) __nv_bfloat16 g_Alo[N_B * L_PAD * C_DIM];
__device__ __align__(16) __nv_bfloat16 g_Bhi[N_B * L_PAD * C_DIM];
__device__ __align__(16) __nv_bfloat16 g_Blo[N_B * L_PAD * C_DIM];

// ===========================================================================
// helpers
// ===========================================================================
__device__ __forceinline__ uint32_t smem_u32(const void* p) {
    uint32_t a;
    asm("{ .reg .u64 t; cvta.to.shared.u64 t, %1; cvt.u32.u64 %0, t; }"
        : "=r"(a) : "l"(p));
    return a;
}
__device__ __forceinline__ void cp_async16(uint32_t dst, const void* src) {
    asm volatile("cp.async.cg.shared.global [%0], [%1], 16;"
                 :: "r"(dst), "l"(src));
}
#define CP_COMMIT() asm volatile("cp.async.commit_group;")
#define CP_WAIT(n)  asm volatile("cp.async.wait_group %0;" :: "n"(n))

__device__ __forceinline__ void ldsm4(uint32_t* r, uint32_t addr) {
    asm volatile("ldmatrix.sync.aligned.m8n8.x4.shared.b16 {%0,%1,%2,%3}, [%4];"
                 : "=r"(r[0]), "=r"(r[1]), "=r"(r[2]), "=r"(r[3]) : "r"(addr));
}
__device__ __forceinline__ void mma16816(float* d, const uint32_t* a,
                                         uint32_t b0, uint32_t b1) {
    asm volatile(
        "mma.sync.aligned.m16n8k16.row.col.f32.bf16.bf16.f32 "
        "{%0,%1,%2,%3}, {%4,%5,%6,%7}, {%8,%9}, {%0,%1,%2,%3};"
        : "+f"(d[0]), "+f"(d[1]), "+f"(d[2]), "+f"(d[3])
        : "r"(a[0]), "r"(a[1]), "r"(a[2]), "r"(a[3]), "r"(b0), "r"(b1));
}

// ===========================================================================
// 0) zero the accumulators (graph replay determinism)
// ===========================================================================
__global__ void zero_kernel() {
    int i = blockIdx.x * 256 + threadIdx.x;
    if (i < N_B * L_DIM) {
        g_rowsum[i] = 0.0f; g_colsum[i] = 0.0f;
        g_colmax[i] = 0.0f; g_rowpack[i] = 0ull;
    }
}

// ===========================================================================
// 1) fp32 -> bf16 hi/lo split
// ===========================================================================
__device__ __forceinline__ uint32_t pack2(__nv_bfloat16 a, __nv_bfloat16 b) {
    __nv_bfloat162 t(a, b);
    return *(uint32_t*)&t;
}
__global__ void convert_kernel(const float* __restrict__ A,
                               const float* __restrict__ B) {
    const int i = blockIdx.x * 256 + threadIdx.x;   // quad index
    const int total = N_B * L_DIM * C_DIM / 4;
    if (i >= total) return;
    const int row = i >> 6;            // 64 quads per 256-elem row
    const int q   = i & 63;
    const int n = row / L_DIM, l = row % L_DIM;
    const size_t dst = ((size_t)n * L_PAD + l) * C_DIM + q * 4;

    float4 a = *(const float4*)(A + (size_t)i * 4);
    __nv_bfloat16 hx = __float2bfloat16(a.x), hy = __float2bfloat16(a.y);
    __nv_bfloat16 hz = __float2bfloat16(a.z), hw = __float2bfloat16(a.w);
    __nv_bfloat16 lx = __float2bfloat16(a.x - __bfloat162float(hx));
    __nv_bfloat16 ly = __float2bfloat16(a.y - __bfloat162float(hy));
    __nv_bfloat16 lz = __float2bfloat16(a.z - __bfloat162float(hz));
    __nv_bfloat16 lw = __float2bfloat16(a.w - __bfloat162float(hw));
    *(uint2*)(g_Ahi + dst) = make_uint2(pack2(hx, hy), pack2(hz, hw));
    *(uint2*)(g_Alo + dst) = make_uint2(pack2(lx, ly), pack2(lz, lw));

    float4 b = *(const float4*)(B + (size_t)i * 4);
    hx = __float2bfloat16(b.x); hy = __float2bfloat16(b.y);
    hz = __float2bfloat16(b.z); hw = __float2bfloat16(b.w);
    lx = __float2bfloat16(b.x - __bfloat162float(hx));
    ly = __float2bfloat16(b.y - __bfloat162float(hy));
    lz = __float2bfloat16(b.z - __bfloat162float(hz));
    lw = __float2bfloat16(b.w - __bfloat162float(hw));
    *(uint2*)(g_Bhi + dst) = make_uint2(pack2(hx, hy), pack2(hz, hw));
    *(uint2*)(g_Blo + dst) = make_uint2(pack2(lx, ly), pack2(lz, lw));
}

// ===========================================================================
// 2) mma.sync bf16 GEMM, split precision (hi*hi + hi*lo + lo*hi), fp32 accum.
//    128x128 tile / CTA, 8 warps (2x4), warp tile 64x32, BK=32, cp.async
//    double buffer. Fused epilogue: E = __expf(d*SIM_SCALE), row/col sums.
//    Smem tile pitch 80B (conflict-free for ldmatrix & 16B cp.async).
// ===========================================================================
#define TILE_B   10240          // 128 rows * 80B
#define STAGE_B  (4 * TILE_B)   // Ahi, Alo, Bhi, Blo
#define GEMM_SMEM (2 * STAGE_B) // 81920

__global__ __launch_bounds__(256, 1)
void gemm_mma_kernel(float* __restrict__ E) {
    extern __shared__ char smem[];
    __shared__ float sRow[128];
    __shared__ float sCol[128];

    const int tid  = threadIdx.x;
    const int lane = tid & 31;
    const int wid  = tid >> 5;
    const int warp_m = wid >> 2;       // 0..1
    const int warp_n = wid & 3;        // 0..3
    const int n    = blockIdx.z;
    const int brow = blockIdx.y * 128;
    const int bcol = blockIdx.x * 128;
    const uint32_t sb = smem_u32(smem);

    if (tid < 128) { sRow[tid] = 0.f; sCol[tid] = 0.f; }

    const char* srcs[4] = {
        (const char*)(g_Ahi + ((size_t)n * L_PAD + brow) * C_DIM),
        (const char*)(g_Alo + ((size_t)n * L_PAD + brow) * C_DIM),
        (const char*)(g_Bhi + ((size_t)n * L_PAD + bcol) * C_DIM),
        (const char*)(g_Blo + ((size_t)n * L_PAD + bcol) * C_DIM),
    };

    float acc[4][4][4];
    #pragma unroll
    for (int a = 0; a < 4; a++)
        #pragma unroll
        for (int b = 0; b < 4; b++)
            #pragma unroll
            for (int c = 0; c < 4; c++) acc[a][b][c] = 0.f;

    // ---- prefetch helper: chunk c -> stage c&1 (2048 x 16B units) ----
    auto prefetch = [&](int c) {
        const uint32_t st = sb + (c & 1) * STAGE_B;
        const int k0b = c * 64;                    // 32 bf16 = 64 bytes
        #pragma unroll
        for (int u = 0; u < 8; u++) {
            int i = tid + u * 256;
            int t = i >> 9, idx = i & 511, r = idx >> 2, cc = idx & 3;
            cp_async16(st + t * TILE_B + r * 80 + cc * 16,
                       srcs[t] + (size_t)r * 512 + k0b + cc * 16);
        }
    };

    prefetch(0); CP_COMMIT();

    #pragma unroll 1
    for (int c = 0; c < 8; c++) {
        if (c < 7) { prefetch(c + 1); CP_COMMIT(); CP_WAIT(1); }
        else       { CP_WAIT(0); }
        __syncthreads();

        const uint32_t st = sb + (c & 1) * STAGE_B;
        #pragma unroll
        for (int ks = 0; ks < 2; ks++) {
            // A fragments: rows warp_m*64 + tm*16 + (lane&15); k half by lane>>4
            uint32_t aoff = (uint32_t)((warp_m * 64 + (lane & 15)) * 80
                                       + ks * 32 + (lane >> 4) * 16);
            uint32_t ahi[4][4], alo[4][4];
            #pragma unroll
            for (int tm = 0; tm < 4; tm++) {
                ldsm4(ahi[tm], st + aoff + tm * (16 * 80));
                ldsm4(alo[tm], st + TILE_B + aoff + tm * (16 * 80));
            }
            // B fragments: x4 covers 2 n-tiles (16 n x 16 k)
            uint32_t boff = (uint32_t)((warp_n * 32 + (lane & 7) + ((lane >> 4) << 3)) * 80
                                       + ks * 32 + (((lane >> 3) & 1) << 4));
            uint32_t bhi[2][4], blo[2][4];
            #pragma unroll
            for (int p = 0; p < 2; p++) {
                ldsm4(bhi[p], st + 2 * TILE_B + boff + p * (16 * 80));
                ldsm4(blo[p], st + 3 * TILE_B + boff + p * (16 * 80));
            }
            #pragma unroll
            for (int tm = 0; tm < 4; tm++) {
                #pragma unroll
                for (int tn = 0; tn < 4; tn++) {
                    const int p = tn >> 1, h = (tn & 1) * 2;
                    mma16816(acc[tm][tn], ahi[tm], bhi[p][h], bhi[p][h + 1]);
                    mma16816(acc[tm][tn], ahi[tm], blo[p][h], blo[p][h + 1]);
                    mma16816(acc[tm][tn], alo[tm], bhi[p][h], bhi[p][h + 1]);
                }
            }
        }
        __syncthreads();
    }

    // ---- epilogue ----
    // acc mapping: d0,d1 -> row lane>>2, cols (lane&3)*2, +1 ; d2,d3 -> row+8
    float cp[4][2];
    #pragma unroll
    for (int tn = 0; tn < 4; tn++) { cp[tn][0] = 0.f; cp[tn][1] = 0.f; }

    float* Eb = E + (size_t)n * L_DIM * S_DIM;
    #pragma unroll
    for (int tm = 0; tm < 4; tm++) {
        const int lr0 = warp_m * 64 + tm * 16 + (lane >> 2);
        const int gr0 = brow + lr0, gr1 = gr0 + 8;
        const bool ok0 = gr0 < L_DIM, ok1 = gr1 < L_DIM;
        float rs0 = 0.f, rs1 = 0.f;
        float* p0 = Eb + (size_t)gr0 * S_DIM;
        float* p1 = Eb + (size_t)gr1 * S_DIM;
        #pragma unroll
        for (int tn = 0; tn < 4; tn++) {
            const int gc = bcol + warp_n * 32 + tn * 8 + (lane & 3) * 2;
            const bool okc = gc < S_DIM;
            float e0 = __expf(acc[tm][tn][0] * SIM_SCALE);
            float e1 = __expf(acc[tm][tn][1] * SIM_SCALE);
            float e2 = __expf(acc[tm][tn][2] * SIM_SCALE);
            float e3 = __expf(acc[tm][tn][3] * SIM_SCALE);
            if (ok0 && okc) *(float2*)(p0 + gc) = make_float2(e0, e1);
            if (ok1 && okc) *(float2*)(p1 + gc) = make_float2(e2, e3);
            float m00 = (ok0 && okc) ? e0 : 0.f;
            float m01 = (ok0 && okc) ? e1 : 0.f;
            float m10 = (ok1 && okc) ? e2 : 0.f;
            float m11 = (ok1 && okc) ? e3 : 0.f;
            rs0 += m00 + m01; rs1 += m10 + m11;
            cp[tn][0] += m00 + m10; cp[tn][1] += m01 + m11;
        }
        rs0 += __shfl_xor_sync(0xffffffffu, rs0, 1);
        rs0 += __shfl_xor_sync(0xffffffffu, rs0, 2);
        rs1 += __shfl_xor_sync(0xffffffffu, rs1, 1);
        rs1 += __shfl_xor_sync(0xffffffffu, rs1, 2);
        if ((lane & 3) == 0) {
            atomicAdd(&sRow[lr0], rs0);
            atomicAdd(&sRow[lr0 + 8], rs1);
        }
    }
    #pragma unroll
    for (int tn = 0; tn < 4; tn++) {
        float cx = cp[tn][0], cy = cp[tn][1];
        cx += __shfl_xor_sync(0xffffffffu, cx, 4);
        cx += __shfl_xor_sync(0xffffffffu, cx, 8);
        cx += __shfl_xor_sync(0xffffffffu, cx, 16);
        cy += __shfl_xor_sync(0xffffffffu, cy, 4);
        cy += __shfl_xor_sync(0xffffffffu, cy, 8);
        cy += __shfl_xor_sync(0xffffffffu, cy, 16);
        if (lane < 4) {
            const int lc = warp_n * 32 + tn * 8 + lane * 2;
            atomicAdd(&sCol[lc], cx);
            atomicAdd(&sCol[lc + 1], cy);
        }
    }
    __syncthreads();
    if (tid < 128) {
        const int gr = brow + tid;
        if (gr < L_DIM) atomicAdd(&g_rowsum[n * L_DIM + gr], sRow[tid]);
        const int gc = bcol + tid;
        if (gc < S_DIM) atomicAdd(&g_colsum[n * S_DIM + gc], sCol[tid]);
    }
}

// ===========================================================================
// 3) reciprocals
// ===========================================================================
__global__ void inv_kernel() {
    int i = blockIdx.x * 256 + threadIdx.x;
    if (i < N_B * L_DIM) {
        g_invrow[i] = 1.0f / g_rowsum[i];
        g_invcol[i] = 1.0f / g_colsum[i];
    }
}

// ===========================================================================
// 4) fused norm pass: conf = (E*invr)*(E*invc) in place; per-row packed
//    max/argmax via u64 atomicMax; per-col max via int atomicMax.
//    Block = 32-col strip x all rows of one batch. Thread = (col4, rowlane).
// ===========================================================================
__global__ __launch_bounds__(256)
void norm_pass_kernel(float* __restrict__ conf) {
    const int n  = blockIdx.y;
    const int t  = threadIdx.x;
    const int c4 = blockIdx.x * 8 + (t & 7);     // float4 col index < 1200
    const int r0 = t >> 3;                        // 0..31
    float4* base = (float4*)(conf + (size_t)n * L_DIM * S_DIM) + c4;
    const float4 ic = ((const float4*)(g_invcol + n * S_DIM))[c4];
    const float* invrow = g_invrow + n * L_DIM;
    unsigned long long* rowpack = g_rowpack + n * L_DIM;
    const int colbase = c4 * 4;

    float4 cm = make_float4(0.f, 0.f, 0.f, 0.f);
    #pragma unroll 2
    for (int it = 0; it < 150; it++) {
        const int row = r0 + it * 32;
        const float ir = invrow[row];
        float4 e = base[(size_t)row * 1200];
        float4 v;
        v.x = (e.x * ir) * (e.x * ic.x);
        v.y = (e.y * ir) * (e.y * ic.y);
        v.z = (e.z * ir) * (e.z * ic.z);
        v.w = (e.w * ir) * (e.w * ic.w);
        base[(size_t)row * 1200] = v;
        cm.x = fmaxf(cm.x, v.x); cm.y = fmaxf(cm.y, v.y);
        cm.z = fmaxf(cm.z, v.z); cm.w = fmaxf(cm.w, v.w);

        float bv = v.x; int bi = colbase;
        if (v.y > bv) { bv = v.y; bi = colbase + 1; }
        if (v.z > bv) { bv = v.z; bi = colbase + 2; }
        if (v.w > bv) { bv = v.w; bi = colbase + 3; }
        unsigned long long p =
            ((unsigned long long)__float_as_uint(bv) << 32) | (unsigned)(~bi);
        unsigned long long q;
        q = __shfl_xor_sync(0xffffffffu, p, 1); p = p > q ? p : q;
        q = __shfl_xor_sync(0xffffffffu, p, 2); p = p > q ? p : q;
        q = __shfl_xor_sync(0xffffffffu, p, 4); p = p > q ? p : q;
        if ((t & 7) == 0) atomicMax(&rowpack[row], p);
    }
    int* cmp = (int*)(g_colmax + n * S_DIM + colbase);
    atomicMax(cmp + 0, __float_as_int(cm.x));
    atomicMax(cmp + 1, __float_as_int(cm.y));
    atomicMax(cmp + 2, __float_as_int(cm.z));
    atomicMax(cmp + 3, __float_as_int(cm.w));
}

// ===========================================================================
// 5) match extraction (O(1) per row)
// ===========================================================================
__global__ void match_kernel(float* __restrict__ out) {
    const int i = blockIdx.x * 256 + threadIdx.x;
    if (i >= N_B * L_DIM) return;
    const int n = i / L_DIM;
    const int l = i % L_DIM;

    const unsigned long long p = g_rowpack[i];
    const float v = __uint_as_float((unsigned)(p >> 32));
    const int   j = (int)(~(unsigned)(p & 0xffffffffu));

    const int y0 = l / W0, x0 = l % W0;
    const int y1 = j / W1, x1 = j % W1;
    const bool b0 = (y0 >= BRD) && (y0 < H0 - BRD) && (x0 >= BRD) && (x0 < W0 - BRD);
    const bool b1 = (y1 >= BRD) && (y1 < H1 - BRD) && (x1 >= BRD) && (x1 < W1 - BRD);
    const bool mv = (v > THR_V) && b0 && b1 && (v == g_colmax[n * S_DIM + j]);

    const int jid = mv ? j : 0;

    const size_t base = (size_t)N_B * L_DIM * S_DIM;
    const int NL = N_B * L_DIM;
    out[base + i]                  = mv ? 1.0f : 0.0f;   // mask_v
    out[base + NL + i]             = (float)jid;         // j_ids
    out[base + 2 * NL + 2 * i]     = (float)(jid % W1);  // mkpts1_c x
    out[base + 2 * NL + 2 * i + 1] = (float)(jid / W1);  // mkpts1_c y
    out[base + 4 * NL + i]         = mv ? v : 0.0f;      // mconf
}

// ===========================================================================
// launch
// ===========================================================================
extern "C" void kernel_launch(void* const* d_in, const int* in_sizes, int n_in,
                              void* d_out, int out_size) {
    const float* feat0 = (const float*)d_in[0];
    const float* feat1 = (const float*)d_in[1];
    float* out = (float*)d_out;

    static bool attr_set = false;
    if (!attr_set) {
        cudaFuncSetAttribute(gemm_mma_kernel,
                             cudaFuncAttributeMaxDynamicSharedMemorySize, GEMM_SMEM);
        attr_set = true;
    }

    zero_kernel<<<(N_B * L_DIM + 255) / 256, 256>>>();
    convert_kernel<<<(N_B * L_DIM * C_DIM / 4 + 255) / 256, 256>>>(feat0, feat1);

    dim3 gGrid(NTILES, NTILES, N_B);
    gemm_mma_kernel<<<gGrid, 256, GEMM_SMEM>>>(out);

    inv_kernel<<<(N_B * L_DIM + 255) / 256, 256>>>();

    dim3 nGrid(150, N_B);
    norm_pass_kernel<<<nGrid, 256>>>(out);

    match_kernel<<<(N_B * L_DIM + 255) / 256, 256>>>(out);
}